// round 7
// baseline (speedup 1.0000x reference)
#include <cuda_runtime.h>
#include <cuda_bf16.h>
#include <cstdint>

// ---------------- problem constants ----------------
#define D_MODEL 1024
#define Hh      16
#define Nn      4
#define NSKEW   6
#define Bb      4
#define Tt      4096
#define NROWS   (Bb*Tt)                    // 16384
#define NCOLS1  (Hh*NSKEW + Hh*Nn)         // 160
#define VOFF    (Hh*NSKEW)                 // 96
#define HN      (Hh*Nn)                    // 64
#define CHAINS  (Bb*Hh)                    // 64
#define CHUNK   8
#define NCHUNK  (Tt/CHUNK)                 // 512

// ---------------- scratch ----------------
__device__ __nv_bfloat16 g_Bt1H[NCOLS1*D_MODEL];   // Wcat^T hi
__device__ __nv_bfloat16 g_Bt1L[NCOLS1*D_MODEL];   // Wcat^T lo
__device__ __nv_bfloat16 g_Bt2H[D_MODEL*HN];       // Wo^T hi
__device__ __nv_bfloat16 g_Bt2L[D_MODEL*HN];       // Wo^T lo
__device__ float g_SV  [NROWS*NCOLS1];
__device__ float g_L   [CHAINS*Tt*16];
__device__ float g_Ctot[CHAINS*NCHUNK*16];
__device__ __nv_bfloat16 g_RotH[NROWS*HN];
__device__ __nv_bfloat16 g_RotL[NROWS*HN];

// ---------------- bf16 helpers ----------------
__device__ __forceinline__ void mma_bf16(float* c,
                                         uint32_t a0, uint32_t a1, uint32_t a2, uint32_t a3,
                                         uint32_t b0, uint32_t b1) {
    asm volatile(
        "mma.sync.aligned.m16n8k16.row.col.f32.bf16.bf16.f32 "
        "{%0,%1,%2,%3}, {%4,%5,%6,%7}, {%8,%9}, {%0,%1,%2,%3};"
        : "+f"(c[0]), "+f"(c[1]), "+f"(c[2]), "+f"(c[3])
        : "r"(a0), "r"(a1), "r"(a2), "r"(a3), "r"(b0), "r"(b1));
}

__device__ __forceinline__ void split_pack(float4 v, uint2& hi, uint2& lo) {
    __nv_bfloat16 hx = __float2bfloat16_rn(v.x);
    __nv_bfloat16 hy = __float2bfloat16_rn(v.y);
    __nv_bfloat16 hz = __float2bfloat16_rn(v.z);
    __nv_bfloat16 hw = __float2bfloat16_rn(v.w);
    __nv_bfloat16 lx = __float2bfloat16_rn(v.x - __bfloat162float(hx));
    __nv_bfloat16 ly = __float2bfloat16_rn(v.y - __bfloat162float(hy));
    __nv_bfloat16 lz = __float2bfloat16_rn(v.z - __bfloat162float(hz));
    __nv_bfloat16 lw = __float2bfloat16_rn(v.w - __bfloat162float(hw));
    hi.x = (uint32_t)__bfloat16_as_ushort(hx) | ((uint32_t)__bfloat16_as_ushort(hy) << 16);
    hi.y = (uint32_t)__bfloat16_as_ushort(hz) | ((uint32_t)__bfloat16_as_ushort(hw) << 16);
    lo.x = (uint32_t)__bfloat16_as_ushort(lx) | ((uint32_t)__bfloat16_as_ushort(ly) << 16);
    lo.y = (uint32_t)__bfloat16_as_ushort(lz) | ((uint32_t)__bfloat16_as_ushort(lw) << 16);
}

// ---------------- bf16-split HMMA GEMM (double-buffered, pre-split operands) ----------
// C[M,NTOT] = A[M,KTOT] @ Bt[NTOT,KTOT]^T.
// ASPLIT=false: A is fp32 (converted inline). ASPLIT=true: A pre-split bf16 hi/lo.
// B is always pre-split bf16 hi/lo (mainloop fill = pure 16B copies).
template<int BN, int NTOT, int KTOT, bool ASPLIT>
__global__ void __launch_bounds__(256) gemm_bf16_kernel(
    const float* __restrict__ A32,
    const __nv_bfloat16* __restrict__ AH, const __nv_bfloat16* __restrict__ AL,
    const __nv_bfloat16* __restrict__ BH, const __nv_bfloat16* __restrict__ BL,
    float* __restrict__ C)
{
    constexpr int BM = 128, KC = 16;
    constexpr int NSTEP = KTOT / KC;
    constexpr int WN = BN / 2;
    constexpr int MT = 2, NT = WN / 8;
    constexpr int RS = 48;                  // 32B bf16 data + 16B pad per row
    constexpr int STG = (2*BM + 2*BN) * RS;
    constexpr int AHIo = 0, ALOo = BM*RS, BHIo = 2*BM*RS, BLOo = 2*BM*RS + BN*RS;
    constexpr int NB = BN * 2;              // uint4 slots per B array
    constexpr int MAXB = (NB + 255) / 256;

    extern __shared__ __align__(16) unsigned char smem[];

    const int tid = threadIdx.x, warpw = tid >> 5, lane = tid & 31;
    const int brow = blockIdx.y * BM, bcol = blockIdx.x * BN;
    const int wm0 = (warpw >> 1) * 32, wn0 = (warpw & 1) * WN;
    const int gr = lane >> 2, lc = lane & 3;

    float acc[MT][NT][4];
    #pragma unroll
    for (int i = 0; i < MT; i++)
        #pragma unroll
        for (int j = 0; j < NT; j++)
            #pragma unroll
            for (int e = 0; e < 4; e++) acc[i][j][e] = 0.f;

    float4 apf[2];
    uint4  ahpf, alpf;
    uint4  bhpf[MAXB], blpf[MAXB];

    auto loadA = [&](int kk) {
        if (ASPLIT) {
            int row = tid >> 1, q = tid & 1;               // BM*2 == 256 slots
            ahpf = *(const uint4*)(AH + (size_t)(brow + row)*KTOT + kk + q*8);
            alpf = *(const uint4*)(AL + (size_t)(brow + row)*KTOT + kk + q*8);
        } else {
            #pragma unroll
            for (int r = 0; r < 2; r++) {
                int e = tid + r*256; int row = e >> 2, q = e & 3;
                apf[r] = *(const float4*)(A32 + (size_t)(brow + row)*KTOT + kk + q*4);
            }
        }
    };
    auto loadB = [&](int kk) {
        #pragma unroll
        for (int r = 0; r < MAXB; r++) {
            int e = tid + r*256;
            if (e < NB) {
                int row = e >> 1, q = e & 1;
                bhpf[r] = *(const uint4*)(BH + (size_t)(bcol + row)*KTOT + kk + q*8);
                blpf[r] = *(const uint4*)(BL + (size_t)(bcol + row)*KTOT + kk + q*8);
            }
        }
    };
    auto storeTiles = [&](unsigned char* st) {
        if (ASPLIT) {
            int row = tid >> 1, q = tid & 1;
            *(uint4*)&st[AHIo + row*RS + q*16] = ahpf;
            *(uint4*)&st[ALOo + row*RS + q*16] = alpf;
        } else {
            #pragma unroll
            for (int r = 0; r < 2; r++) {
                int e = tid + r*256; int row = e >> 2, q = e & 3;
                uint2 hi, lo; split_pack(apf[r], hi, lo);
                *(uint2*)&st[AHIo + row*RS + q*8] = hi;
                *(uint2*)&st[ALOo + row*RS + q*8] = lo;
            }
        }
        #pragma unroll
        for (int r = 0; r < MAXB; r++) {
            int e = tid + r*256;
            if (e < NB) {
                int row = e >> 1, q = e & 1;
                *(uint4*)&st[BHIo + row*RS + q*16] = bhpf[r];
                *(uint4*)&st[BLOo + row*RS + q*16] = blpf[r];
            }
        }
    };

    loadA(0); loadB(0);
    storeTiles(smem);

    for (int s = 0; s < NSTEP; s++) {
        __syncthreads();
        const unsigned char* cur = smem + (s & 1) * STG;
        if (s + 1 < NSTEP) { loadA((s+1)*KC); loadB((s+1)*KC); }

        uint32_t ah[MT][4], al[MT][4];
        #pragma unroll
        for (int mt = 0; mt < MT; mt++) {
            int ro = (wm0 + mt*16 + gr) * RS + lc*4;
            ah[mt][0] = *(const uint32_t*)&cur[AHIo + ro];
            ah[mt][1] = *(const uint32_t*)&cur[AHIo + ro + 8*RS];
            ah[mt][2] = *(const uint32_t*)&cur[AHIo + ro + 16];
            ah[mt][3] = *(const uint32_t*)&cur[AHIo + ro + 8*RS + 16];
            al[mt][0] = *(const uint32_t*)&cur[ALOo + ro];
            al[mt][1] = *(const uint32_t*)&cur[ALOo + ro + 8*RS];
            al[mt][2] = *(const uint32_t*)&cur[ALOo + ro + 16];
            al[mt][3] = *(const uint32_t*)&cur[ALOo + ro + 8*RS + 16];
        }
        #pragma unroll
        for (int nt = 0; nt < NT; nt++) {
            int ro = (wn0 + nt*8 + gr) * RS + lc*4;
            uint32_t bh0 = *(const uint32_t*)&cur[BHIo + ro];
            uint32_t bh1 = *(const uint32_t*)&cur[BHIo + ro + 16];
            uint32_t bl0 = *(const uint32_t*)&cur[BLOo + ro];
            uint32_t bl1 = *(const uint32_t*)&cur[BLOo + ro + 16];
            #pragma unroll
            for (int mt = 0; mt < MT; mt++) {
                mma_bf16(acc[mt][nt], ah[mt][0], ah[mt][1], ah[mt][2], ah[mt][3], bh0, bh1);
                mma_bf16(acc[mt][nt], al[mt][0], al[mt][1], al[mt][2], al[mt][3], bh0, bh1);
                mma_bf16(acc[mt][nt], ah[mt][0], ah[mt][1], ah[mt][2], ah[mt][3], bl0, bl1);
            }
        }
        if (s + 1 < NSTEP)
            storeTiles(smem + ((s + 1) & 1) * STG);
    }

    #pragma unroll
    for (int mt = 0; mt < MT; mt++) {
        int r0 = brow + wm0 + mt*16 + gr;
        #pragma unroll
        for (int nt = 0; nt < NT; nt++) {
            int c0 = bcol + wn0 + nt*8 + 2*lc;
            *(float2*)(C + (size_t)r0*NTOT + c0)       = make_float2(acc[mt][nt][0], acc[mt][nt][1]);
            *(float2*)(C + (size_t)(r0 + 8)*NTOT + c0) = make_float2(acc[mt][nt][2], acc[mt][nt][3]);
        }
    }
}

// ---------------- K0: transpose/concat + bf16-split weights ----------------
__global__ void prep_kernel(const float* __restrict__ Wskew,
                            const float* __restrict__ Wv,
                            const float* __restrict__ Wo) {
    int i = blockIdx.x*blockDim.x + threadIdx.x;
    if (i < NCOLS1*D_MODEL) {
        int n = i >> 10, k = i & 1023;
        float v = (n < VOFF) ? Wskew[k*VOFF + n] : Wv[k*HN + (n - VOFF)];
        __nv_bfloat16 h = __float2bfloat16_rn(v);
        g_Bt1H[i] = h;
        g_Bt1L[i] = __float2bfloat16_rn(v - __bfloat162float(h));
    } else {
        int j = i - NCOLS1*D_MODEL;
        if (j < D_MODEL*HN) {
            int n = j >> 6, k = j & 63;
            float v = Wo[k*D_MODEL + n];
            __nv_bfloat16 h = __float2bfloat16_rn(v);
            g_Bt2H[j] = h;
            g_Bt2L[j] = __float2bfloat16_rn(v - __bfloat162float(h));
        }
    }
}

// ---------------- mm4 ----------------
__device__ __forceinline__ void mm4(const float* __restrict__ A,
                                    const float* __restrict__ B,
                                    float* __restrict__ C) {
    #pragma unroll
    for (int i = 0; i < 4; i++)
        #pragma unroll
        for (int j = 0; j < 4; j++)
            C[i*4+j] = A[i*4+0]*B[0*4+j] + A[i*4+1]*B[1*4+j]
                     + A[i*4+2]*B[2*4+j] + A[i*4+3]*B[3*4+j];
}

// ---------------- K2: fused expm + chunk-local scan ----------------
__global__ void __launch_bounds__(256) expm_scan_kernel() {
    int g = blockIdx.x*blockDim.x + threadIdx.x;
    if (g >= CHAINS*NCHUNK) return;
    int chunk = g & (NCHUNK-1);
    int chain = g >> 9;                    // NCHUNK == 512
    int b     = chain >> 4;
    int h     = chain & 15;
    int t0    = chunk * CHUNK;

    const float* sv = g_SV + (size_t)(b*Tt + t0)*NCOLS1 + h*NSKEW;
    float* Lb = g_L + ((size_t)chain*Tt + t0)*16;

    float m[16];
    #pragma unroll
    for (int e = 0; e < 16; e++) m[e] = (e % 5 == 0) ? 1.0f : 0.0f;

    for (int t = 0; t < CHUNK; t++) {
        float2 s01 = *(const float2*)(sv + (size_t)t*NCOLS1);
        float2 s23 = *(const float2*)(sv + (size_t)t*NCOLS1 + 2);
        float2 s45 = *(const float2*)(sv + (size_t)t*NCOLS1 + 4);
        float a01 = s01.x, a02 = s01.y, a03 = s23.x;
        float a12 = s23.y, a13 = s45.x, a23 = s45.y;

        float fr = sqrtf(2.0f*(a01*a01 + a02*a02 + a03*a03 +
                               a12*a12 + a13*a13 + a23*a23));
        int sft = 0;
        float f = fr;
        while (f > 0.25f && sft < 32) { f *= 0.5f; sft++; }
        float sc = ldexpf(1.0f, -sft);

        float A[16] = {  0.f,  a01,  a02,  a03,
                        -a01,  0.f,  a12,  a13,
                        -a02, -a12,  0.f,  a23,
                        -a03, -a13, -a23,  0.f };
        #pragma unroll
        for (int e = 0; e < 16; e++) A[e] *= sc;

        float Tm[16], Tmp[16];
        #pragma unroll
        for (int e = 0; e < 16; e++)
            Tm[e] = A[e]*(1.0f/8.0f) + ((e % 5 == 0) ? 1.0f : 0.0f);
        #pragma unroll
        for (int k = 7; k >= 1; k--) {
            mm4(A, Tm, Tmp);
            float inv = 1.0f/(float)k;
            #pragma unroll
            for (int e = 0; e < 16; e++)
                Tm[e] = Tmp[e]*inv + ((e % 5 == 0) ? 1.0f : 0.0f);
        }
        for (int q = 0; q < sft; q++) {
            mm4(Tm, Tm, Tmp);
            #pragma unroll
            for (int e = 0; e < 16; e++) Tm[e] = Tmp[e];
        }

        float nm[16];
        mm4(Tm, m, nm);
        #pragma unroll
        for (int e = 0; e < 16; e++) m[e] = nm[e];

        float4* Lo = (float4*)(Lb + (size_t)t*16);
        Lo[0] = make_float4(m[0],  m[1],  m[2],  m[3]);
        Lo[1] = make_float4(m[4],  m[5],  m[6],  m[7]);
        Lo[2] = make_float4(m[8],  m[9],  m[10], m[11]);
        Lo[3] = make_float4(m[12], m[13], m[14], m[15]);
    }

    float4* Cb = (float4*)(g_Ctot + ((size_t)chain*NCHUNK + chunk)*16);
    Cb[0] = make_float4(m[0],  m[1],  m[2],  m[3]);
    Cb[1] = make_float4(m[4],  m[5],  m[6],  m[7]);
    Cb[2] = make_float4(m[8],  m[9],  m[10], m[11]);
    Cb[3] = make_float4(m[12], m[13], m[14], m[15]);
}

// ---------------- K3: fused chunk-prefix (shuffle scan) + rotate ----------------
// One block per chain (512 threads = 512 chunks). Shuffle-based hierarchical
// scan (5 warp stages + 16-wide warp-0 stage, 3 barriers), then the rotate
// phase remaps threads to timesteps (coalesced g_L reads) with P-matrices in
// smem. Writes rotated values pre-split to bf16 hi/lo for gemm2.
__global__ void __launch_bounds__(NCHUNK) prefix_rotate_kernel() {
    __shared__ float smW[16*16];
    __shared__ float smP[NCHUNK*17];
    const int i     = threadIdx.x;
    const int chain = blockIdx.x;
    const int warp  = i >> 5, lane = i & 31;
    const int b     = chain >> 4, h = chain & 15;

    float M[16];
    {
        const float* Cb = g_Ctot + ((size_t)chain*NCHUNK + i)*16;
        #pragma unroll
        for (int e = 0; e < 16; e++) M[e] = Cb[e];
    }

    // warp-level inclusive scan (newer on the left)
    #pragma unroll
    for (int d = 1; d < 32; d <<= 1) {
        float P[16];
        #pragma unroll
        for (int e = 0; e < 16; e++) P[e] = __shfl_up_sync(0xffffffffu, M[e], d);
        if (lane >= d) {
            float T[16]; mm4(M, P, T);
            #pragma unroll
            for (int e = 0; e < 16; e++) M[e] = T[e];
        }
    }
    if (lane == 31) {
        #pragma unroll
        for (int e = 0; e < 16; e++) smW[warp*16 + e] = M[e];
    }
    __syncthreads();

    // warp 0 scans the 16 warp totals
    if (warp == 0) {
        float W[16];
        #pragma unroll
        for (int e = 0; e < 16; e++) W[e] = (lane < 16) ? smW[lane*16 + e] : 0.f;
        #pragma unroll
        for (int d = 1; d < 16; d <<= 1) {
            float P[16];
            #pragma unroll
            for (int e = 0; e < 16; e++) P[e] = __shfl_up_sync(0xffffffffu, W[e], d);
            if (lane >= d && lane < 16) {
                float T[16]; mm4(W, P, T);
                #pragma unroll
                for (int e = 0; e < 16; e++) W[e] = T[e];
            }
        }
        if (lane < 16) {
            #pragma unroll
            for (int e = 0; e < 16; e++) smW[lane*16 + e] = W[e];
        }
    }
    __syncthreads();

    // per-thread exclusive prefix P_prev
    float Mp[16];
    #pragma unroll
    for (int e = 0; e < 16; e++) Mp[e] = __shfl_up_sync(0xffffffffu, M[e], 1);
    float P[16];
    if (lane == 0) {
        if (warp == 0) {
            #pragma unroll
            for (int e = 0; e < 16; e++) P[e] = (e % 5 == 0) ? 1.0f : 0.0f;
        } else {
            #pragma unroll
            for (int e = 0; e < 16; e++) P[e] = smW[(warp-1)*16 + e];
        }
    } else if (warp == 0) {
        #pragma unroll
        for (int e = 0; e < 16; e++) P[e] = Mp[e];
    } else {
        float E[16];
        #pragma unroll
        for (int e = 0; e < 16; e++) E[e] = smW[(warp-1)*16 + e];
        mm4(Mp, E, P);
    }
    #pragma unroll
    for (int e = 0; e < 16; e++) smP[i*17 + e] = P[e];
    __syncthreads();

    // rotate: thread handles timesteps t = j*NCHUNK + i (coalesced g_L reads)
    for (int j = 0; j < CHUNK; j++) {
        int t  = j*NCHUNK + i;
        int ch = t >> 3;                 // CHUNK == 8
        const float* Pp = &smP[ch*17];
        int n = b*Tt + t;

        float4 v = *(const float4*)(g_SV + (size_t)n*NCOLS1 + VOFF + h*Nn);
        float u0 = Pp[ 0]*v.x + Pp[ 1]*v.y + Pp[ 2]*v.z + Pp[ 3]*v.w;
        float u1 = Pp[ 4]*v.x + Pp[ 5]*v.y + Pp[ 6]*v.z + Pp[ 7]*v.w;
        float u2 = Pp[ 8]*v.x + Pp[ 9]*v.y + Pp[10]*v.z + Pp[11]*v.w;
        float u3 = Pp[12]*v.x + Pp[13]*v.y + Pp[14]*v.z + Pp[15]*v.w;

        const float* L = g_L + ((size_t)chain*Tt + t)*16;
        float4 l0 = *(const float4*)(L);
        float4 l1 = *(const float4*)(L + 4);
        float4 l2 = *(const float4*)(L + 8);
        float4 l3 = *(const float4*)(L + 12);
        float r0 = l0.x*u0 + l0.y*u1 + l0.z*u2 + l0.w*u3;
        float r1 = l1.x*u0 + l1.y*u1 + l1.z*u2 + l1.w*u3;
        float r2 = l2.x*u0 + l2.y*u1 + l2.z*u2 + l2.w*u3;
        float r3 = l3.x*u0 + l3.y*u1 + l3.z*u2 + l3.w*u3;

        uint2 hi, lo;
        split_pack(make_float4(r0, r1, r2, r3), hi, lo);
        *(uint2*)&g_RotH[(size_t)n*HN + h*Nn] = hi;
        *(uint2*)&g_RotL[(size_t)n*HN + h*Nn] = lo;
    }
}

// ---------------- launcher ----------------
extern "C" void kernel_launch(void* const* d_in, const int* in_sizes, int n_in,
                              void* d_out, int out_size) {
    const float* x     = (const float*)d_in[0];
    const float* Wskew = (const float*)d_in[1];
    const float* Wv    = (const float*)d_in[2];
    const float* Wo    = (const float*)d_in[3];
    float* out = (float*)d_out;

    float *g_SV_p;
    __nv_bfloat16 *b1h, *b1l, *b2h, *b2l, *rh, *rl;
    cudaGetSymbolAddress((void**)&g_SV_p, g_SV);
    cudaGetSymbolAddress((void**)&b1h, g_Bt1H);
    cudaGetSymbolAddress((void**)&b1l, g_Bt1L);
    cudaGetSymbolAddress((void**)&b2h, g_Bt2H);
    cudaGetSymbolAddress((void**)&b2l, g_Bt2L);
    cudaGetSymbolAddress((void**)&rh,  g_RotH);
    cudaGetSymbolAddress((void**)&rl,  g_RotL);

    const int SM1 = 2 * (2*128 + 2*NCOLS1) * 48;   // 55296 B
    const int SM2 = 2 * (2*128 + 2*128) * 48;      // 49152 B
    cudaFuncSetAttribute(gemm_bf16_kernel<NCOLS1, NCOLS1, D_MODEL, false>,
                         cudaFuncAttributeMaxDynamicSharedMemorySize, SM1);
    cudaFuncSetAttribute(gemm_bf16_kernel<128, D_MODEL, HN, true>,
                         cudaFuncAttributeMaxDynamicSharedMemorySize, SM2);

    prep_kernel<<<(NCOLS1*D_MODEL + D_MODEL*HN + 255)/256, 256>>>(Wskew, Wv, Wo);
    gemm_bf16_kernel<NCOLS1, NCOLS1, D_MODEL, false>
        <<<dim3(1, NROWS/128), 256, SM1>>>(x, nullptr, nullptr, b1h, b1l, g_SV_p);
    expm_scan_kernel<<<(CHAINS*NCHUNK + 255)/256, 256>>>();
    prefix_rotate_kernel<<<CHAINS, NCHUNK>>>();
    gemm_bf16_kernel<128, D_MODEL, HN, true>
        <<<dim3(D_MODEL/128, NROWS/128), 256, SM2>>>(nullptr, rh, rl, b2h, b2l, out);
}

// round 8
// speedup vs baseline: 1.0004x; 1.0004x over previous
#include <cuda_runtime.h>
#include <cuda_bf16.h>
#include <cstdint>

// ---------------- problem constants ----------------
#define D_MODEL 1024
#define Hh      16
#define Nn      4
#define NSKEW   6
#define Bb      4
#define Tt      4096
#define NROWS   (Bb*Tt)                    // 16384
#define NCOLS1  (Hh*NSKEW + Hh*Nn)         // 160
#define VOFF    (Hh*NSKEW)                 // 96
#define HN      (Hh*Nn)                    // 64
#define CHAINS  (Bb*Hh)                    // 64
#define CHUNK   8
#define NCHUNK  (Tt/CHUNK)                 // 512

// ---------------- scratch ----------------
__device__ __nv_bfloat16 g_Bt1H[NCOLS1*D_MODEL];   // Wcat^T hi
__device__ __nv_bfloat16 g_Bt1L[NCOLS1*D_MODEL];   // Wcat^T lo
__device__ __nv_bfloat16 g_Bt2H[D_MODEL*HN];       // Wo^T hi
__device__ __nv_bfloat16 g_Bt2L[D_MODEL*HN];       // Wo^T lo
__device__ float g_SV  [NROWS*NCOLS1];
__device__ float g_L   [CHAINS*Tt*16];
__device__ float g_Ctot[CHAINS*NCHUNK*16];
__device__ __nv_bfloat16 g_RotH[NROWS*HN];
__device__ __nv_bfloat16 g_RotL[NROWS*HN];

// ---------------- bf16 helpers ----------------
__device__ __forceinline__ void mma_bf16(float* c,
                                         uint32_t a0, uint32_t a1, uint32_t a2, uint32_t a3,
                                         uint32_t b0, uint32_t b1) {
    asm volatile(
        "mma.sync.aligned.m16n8k16.row.col.f32.bf16.bf16.f32 "
        "{%0,%1,%2,%3}, {%4,%5,%6,%7}, {%8,%9}, {%0,%1,%2,%3};"
        : "+f"(c[0]), "+f"(c[1]), "+f"(c[2]), "+f"(c[3])
        : "r"(a0), "r"(a1), "r"(a2), "r"(a3), "r"(b0), "r"(b1));
}

__device__ __forceinline__ void split_pack(float4 v, uint2& hi, uint2& lo) {
    __nv_bfloat16 hx = __float2bfloat16_rn(v.x);
    __nv_bfloat16 hy = __float2bfloat16_rn(v.y);
    __nv_bfloat16 hz = __float2bfloat16_rn(v.z);
    __nv_bfloat16 hw = __float2bfloat16_rn(v.w);
    __nv_bfloat16 lx = __float2bfloat16_rn(v.x - __bfloat162float(hx));
    __nv_bfloat16 ly = __float2bfloat16_rn(v.y - __bfloat162float(hy));
    __nv_bfloat16 lz = __float2bfloat16_rn(v.z - __bfloat162float(hz));
    __nv_bfloat16 lw = __float2bfloat16_rn(v.w - __bfloat162float(hw));
    hi.x = (uint32_t)__bfloat16_as_ushort(hx) | ((uint32_t)__bfloat16_as_ushort(hy) << 16);
    hi.y = (uint32_t)__bfloat16_as_ushort(hz) | ((uint32_t)__bfloat16_as_ushort(hw) << 16);
    lo.x = (uint32_t)__bfloat16_as_ushort(lx) | ((uint32_t)__bfloat16_as_ushort(ly) << 16);
    lo.y = (uint32_t)__bfloat16_as_ushort(lz) | ((uint32_t)__bfloat16_as_ushort(lw) << 16);
}

// ---------------- bf16-split HMMA GEMM (double-buffered, pre-split operands) ----------
// C[M,NTOT] = A[M,KTOT] @ Bt[NTOT,KTOT]^T.
// ASPLIT=false: A is fp32 (converted inline). ASPLIT=true: A pre-split bf16 hi/lo.
// B is always pre-split bf16 hi/lo (mainloop fill = pure 16B copies).
template<int BN, int NTOT, int KTOT, bool ASPLIT>
__global__ void __launch_bounds__(256) gemm_bf16_kernel(
    const float* __restrict__ A32,
    const __nv_bfloat16* __restrict__ AH, const __nv_bfloat16* __restrict__ AL,
    const __nv_bfloat16* __restrict__ BH, const __nv_bfloat16* __restrict__ BL,
    float* __restrict__ C)
{
    constexpr int BM = 128, KC = 16;
    constexpr int NSTEP = KTOT / KC;
    constexpr int WN = BN / 2;
    constexpr int MT = 2, NT = WN / 8;
    constexpr int RS = 48;                  // 32B bf16 data + 16B pad per row
    constexpr int STG = (2*BM + 2*BN) * RS;
    constexpr int AHIo = 0, ALOo = BM*RS, BHIo = 2*BM*RS, BLOo = 2*BM*RS + BN*RS;
    constexpr int NB = BN * 2;              // uint4 slots per B array
    constexpr int MAXB = (NB + 255) / 256;

    extern __shared__ __align__(16) unsigned char smem[];

    const int tid = threadIdx.x, warpw = tid >> 5, lane = tid & 31;
    const int brow = blockIdx.y * BM, bcol = blockIdx.x * BN;
    const int wm0 = (warpw >> 1) * 32, wn0 = (warpw & 1) * WN;
    const int gr = lane >> 2, lc = lane & 3;

    float acc[MT][NT][4];
    #pragma unroll
    for (int i = 0; i < MT; i++)
        #pragma unroll
        for (int j = 0; j < NT; j++)
            #pragma unroll
            for (int e = 0; e < 4; e++) acc[i][j][e] = 0.f;

    float4 apf[2];
    uint4  ahpf, alpf;
    uint4  bhpf[MAXB], blpf[MAXB];

    auto loadA = [&](int kk) {
        if (ASPLIT) {
            int row = tid >> 1, q = tid & 1;               // BM*2 == 256 slots
            ahpf = *(const uint4*)(AH + (size_t)(brow + row)*KTOT + kk + q*8);
            alpf = *(const uint4*)(AL + (size_t)(brow + row)*KTOT + kk + q*8);
        } else {
            #pragma unroll
            for (int r = 0; r < 2; r++) {
                int e = tid + r*256; int row = e >> 2, q = e & 3;
                apf[r] = *(const float4*)(A32 + (size_t)(brow + row)*KTOT + kk + q*4);
            }
        }
    };
    auto loadB = [&](int kk) {
        #pragma unroll
        for (int r = 0; r < MAXB; r++) {
            int e = tid + r*256;
            if (e < NB) {
                int row = e >> 1, q = e & 1;
                bhpf[r] = *(const uint4*)(BH + (size_t)(bcol + row)*KTOT + kk + q*8);
                blpf[r] = *(const uint4*)(BL + (size_t)(bcol + row)*KTOT + kk + q*8);
            }
        }
    };
    auto storeTiles = [&](unsigned char* st) {
        if (ASPLIT) {
            int row = tid >> 1, q = tid & 1;
            *(uint4*)&st[AHIo + row*RS + q*16] = ahpf;
            *(uint4*)&st[ALOo + row*RS + q*16] = alpf;
        } else {
            #pragma unroll
            for (int r = 0; r < 2; r++) {
                int e = tid + r*256; int row = e >> 2, q = e & 3;
                uint2 hi, lo; split_pack(apf[r], hi, lo);
                *(uint2*)&st[AHIo + row*RS + q*8] = hi;
                *(uint2*)&st[ALOo + row*RS + q*8] = lo;
            }
        }
        #pragma unroll
        for (int r = 0; r < MAXB; r++) {
            int e = tid + r*256;
            if (e < NB) {
                int row = e >> 1, q = e & 1;
                *(uint4*)&st[BHIo + row*RS + q*16] = bhpf[r];
                *(uint4*)&st[BLOo + row*RS + q*16] = blpf[r];
            }
        }
    };

    loadA(0); loadB(0);
    storeTiles(smem);

    for (int s = 0; s < NSTEP; s++) {
        __syncthreads();
        const unsigned char* cur = smem + (s & 1) * STG;
        if (s + 1 < NSTEP) { loadA((s+1)*KC); loadB((s+1)*KC); }

        uint32_t ah[MT][4], al[MT][4];
        #pragma unroll
        for (int mt = 0; mt < MT; mt++) {
            int ro = (wm0 + mt*16 + gr) * RS + lc*4;
            ah[mt][0] = *(const uint32_t*)&cur[AHIo + ro];
            ah[mt][1] = *(const uint32_t*)&cur[AHIo + ro + 8*RS];
            ah[mt][2] = *(const uint32_t*)&cur[AHIo + ro + 16];
            ah[mt][3] = *(const uint32_t*)&cur[AHIo + ro + 8*RS + 16];
            al[mt][0] = *(const uint32_t*)&cur[ALOo + ro];
            al[mt][1] = *(const uint32_t*)&cur[ALOo + ro + 8*RS];
            al[mt][2] = *(const uint32_t*)&cur[ALOo + ro + 16];
            al[mt][3] = *(const uint32_t*)&cur[ALOo + ro + 8*RS + 16];
        }
        #pragma unroll
        for (int nt = 0; nt < NT; nt++) {
            int ro = (wn0 + nt*8 + gr) * RS + lc*4;
            uint32_t bh0 = *(const uint32_t*)&cur[BHIo + ro];
            uint32_t bh1 = *(const uint32_t*)&cur[BHIo + ro + 16];
            uint32_t bl0 = *(const uint32_t*)&cur[BLOo + ro];
            uint32_t bl1 = *(const uint32_t*)&cur[BLOo + ro + 16];
            #pragma unroll
            for (int mt = 0; mt < MT; mt++) {
                mma_bf16(acc[mt][nt], ah[mt][0], ah[mt][1], ah[mt][2], ah[mt][3], bh0, bh1);
                mma_bf16(acc[mt][nt], al[mt][0], al[mt][1], al[mt][2], al[mt][3], bh0, bh1);
                mma_bf16(acc[mt][nt], ah[mt][0], ah[mt][1], ah[mt][2], ah[mt][3], bl0, bl1);
            }
        }
        if (s + 1 < NSTEP)
            storeTiles(smem + ((s + 1) & 1) * STG);
    }

    #pragma unroll
    for (int mt = 0; mt < MT; mt++) {
        int r0 = brow + wm0 + mt*16 + gr;
        #pragma unroll
        for (int nt = 0; nt < NT; nt++) {
            int c0 = bcol + wn0 + nt*8 + 2*lc;
            *(float2*)(C + (size_t)r0*NTOT + c0)       = make_float2(acc[mt][nt][0], acc[mt][nt][1]);
            *(float2*)(C + (size_t)(r0 + 8)*NTOT + c0) = make_float2(acc[mt][nt][2], acc[mt][nt][3]);
        }
    }
}

// ---------------- K0: transpose/concat + bf16-split weights ----------------
__global__ void prep_kernel(const float* __restrict__ Wskew,
                            const float* __restrict__ Wv,
                            const float* __restrict__ Wo) {
    int i = blockIdx.x*blockDim.x + threadIdx.x;
    if (i < NCOLS1*D_MODEL) {
        int n = i >> 10, k = i & 1023;
        float v = (n < VOFF) ? Wskew[k*VOFF + n] : Wv[k*HN + (n - VOFF)];
        __nv_bfloat16 h = __float2bfloat16_rn(v);
        g_Bt1H[i] = h;
        g_Bt1L[i] = __float2bfloat16_rn(v - __bfloat162float(h));
    } else {
        int j = i - NCOLS1*D_MODEL;
        if (j < D_MODEL*HN) {
            int n = j >> 6, k = j & 63;
            float v = Wo[k*D_MODEL + n];
            __nv_bfloat16 h = __float2bfloat16_rn(v);
            g_Bt2H[j] = h;
            g_Bt2L[j] = __float2bfloat16_rn(v - __bfloat162float(h));
        }
    }
}

// ---------------- mm4 ----------------
__device__ __forceinline__ void mm4(const float* __restrict__ A,
                                    const float* __restrict__ B,
                                    float* __restrict__ C) {
    #pragma unroll
    for (int i = 0; i < 4; i++)
        #pragma unroll
        for (int j = 0; j < 4; j++)
            C[i*4+j] = A[i*4+0]*B[0*4+j] + A[i*4+1]*B[1*4+j]
                     + A[i*4+2]*B[2*4+j] + A[i*4+3]*B[3*4+j];
}

// ---------------- K2: fused expm + chunk-local scan ----------------
__global__ void __launch_bounds__(256) expm_scan_kernel() {
    int g = blockIdx.x*blockDim.x + threadIdx.x;
    if (g >= CHAINS*NCHUNK) return;
    int chunk = g & (NCHUNK-1);
    int chain = g >> 9;                    // NCHUNK == 512
    int b     = chain >> 4;
    int h     = chain & 15;
    int t0    = chunk * CHUNK;

    const float* sv = g_SV + (size_t)(b*Tt + t0)*NCOLS1 + h*NSKEW;
    float* Lb = g_L + ((size_t)chain*Tt + t0)*16;

    float m[16];
    #pragma unroll
    for (int e = 0; e < 16; e++) m[e] = (e % 5 == 0) ? 1.0f : 0.0f;

    for (int t = 0; t < CHUNK; t++) {
        float2 s01 = *(const float2*)(sv + (size_t)t*NCOLS1);
        float2 s23 = *(const float2*)(sv + (size_t)t*NCOLS1 + 2);
        float2 s45 = *(const float2*)(sv + (size_t)t*NCOLS1 + 4);
        float a01 = s01.x, a02 = s01.y, a03 = s23.x;
        float a12 = s23.y, a13 = s45.x, a23 = s45.y;

        float fr = sqrtf(2.0f*(a01*a01 + a02*a02 + a03*a03 +
                               a12*a12 + a13*a13 + a23*a23));
        int sft = 0;
        float f = fr;
        while (f > 0.25f && sft < 32) { f *= 0.5f; sft++; }
        float sc = ldexpf(1.0f, -sft);

        float A[16] = {  0.f,  a01,  a02,  a03,
                        -a01,  0.f,  a12,  a13,
                        -a02, -a12,  0.f,  a23,
                        -a03, -a13, -a23,  0.f };
        #pragma unroll
        for (int e = 0; e < 16; e++) A[e] *= sc;

        float Tm[16], Tmp[16];
        #pragma unroll
        for (int e = 0; e < 16; e++)
            Tm[e] = A[e]*(1.0f/8.0f) + ((e % 5 == 0) ? 1.0f : 0.0f);
        #pragma unroll
        for (int k = 7; k >= 1; k--) {
            mm4(A, Tm, Tmp);
            float inv = 1.0f/(float)k;
            #pragma unroll
            for (int e = 0; e < 16; e++)
                Tm[e] = Tmp[e]*inv + ((e % 5 == 0) ? 1.0f : 0.0f);
        }
        for (int q = 0; q < sft; q++) {
            mm4(Tm, Tm, Tmp);
            #pragma unroll
            for (int e = 0; e < 16; e++) Tm[e] = Tmp[e];
        }

        float nm[16];
        mm4(Tm, m, nm);
        #pragma unroll
        for (int e = 0; e < 16; e++) m[e] = nm[e];

        float4* Lo = (float4*)(Lb + (size_t)t*16);
        Lo[0] = make_float4(m[0],  m[1],  m[2],  m[3]);
        Lo[1] = make_float4(m[4],  m[5],  m[6],  m[7]);
        Lo[2] = make_float4(m[8],  m[9],  m[10], m[11]);
        Lo[3] = make_float4(m[12], m[13], m[14], m[15]);
    }

    float4* Cb = (float4*)(g_Ctot + ((size_t)chain*NCHUNK + chunk)*16);
    Cb[0] = make_float4(m[0],  m[1],  m[2],  m[3]);
    Cb[1] = make_float4(m[4],  m[5],  m[6],  m[7]);
    Cb[2] = make_float4(m[8],  m[9],  m[10], m[11]);
    Cb[3] = make_float4(m[12], m[13], m[14], m[15]);
}

// ---------------- K3: fused chunk-prefix (shuffle scan) + rotate ----------------
// One block per chain (512 threads = 512 chunks). Shuffle-based hierarchical
// scan (5 warp stages + 16-wide warp-0 stage, 3 barriers), then the rotate
// phase remaps threads to timesteps (coalesced g_L reads) with P-matrices in
// smem. Writes rotated values pre-split to bf16 hi/lo for gemm2.
__global__ void __launch_bounds__(NCHUNK) prefix_rotate_kernel() {
    __shared__ float smW[16*16];
    __shared__ float smP[NCHUNK*17];
    const int i     = threadIdx.x;
    const int chain = blockIdx.x;
    const int warp  = i >> 5, lane = i & 31;
    const int b     = chain >> 4, h = chain & 15;

    float M[16];
    {
        const float* Cb = g_Ctot + ((size_t)chain*NCHUNK + i)*16;
        #pragma unroll
        for (int e = 0; e < 16; e++) M[e] = Cb[e];
    }

    // warp-level inclusive scan (newer on the left)
    #pragma unroll
    for (int d = 1; d < 32; d <<= 1) {
        float P[16];
        #pragma unroll
        for (int e = 0; e < 16; e++) P[e] = __shfl_up_sync(0xffffffffu, M[e], d);
        if (lane >= d) {
            float T[16]; mm4(M, P, T);
            #pragma unroll
            for (int e = 0; e < 16; e++) M[e] = T[e];
        }
    }
    if (lane == 31) {
        #pragma unroll
        for (int e = 0; e < 16; e++) smW[warp*16 + e] = M[e];
    }
    __syncthreads();

    // warp 0 scans the 16 warp totals
    if (warp == 0) {
        float W[16];
        #pragma unroll
        for (int e = 0; e < 16; e++) W[e] = (lane < 16) ? smW[lane*16 + e] : 0.f;
        #pragma unroll
        for (int d = 1; d < 16; d <<= 1) {
            float P[16];
            #pragma unroll
            for (int e = 0; e < 16; e++) P[e] = __shfl_up_sync(0xffffffffu, W[e], d);
            if (lane >= d && lane < 16) {
                float T[16]; mm4(W, P, T);
                #pragma unroll
                for (int e = 0; e < 16; e++) W[e] = T[e];
            }
        }
        if (lane < 16) {
            #pragma unroll
            for (int e = 0; e < 16; e++) smW[lane*16 + e] = W[e];
        }
    }
    __syncthreads();

    // per-thread exclusive prefix P_prev
    float Mp[16];
    #pragma unroll
    for (int e = 0; e < 16; e++) Mp[e] = __shfl_up_sync(0xffffffffu, M[e], 1);
    float P[16];
    if (lane == 0) {
        if (warp == 0) {
            #pragma unroll
            for (int e = 0; e < 16; e++) P[e] = (e % 5 == 0) ? 1.0f : 0.0f;
        } else {
            #pragma unroll
            for (int e = 0; e < 16; e++) P[e] = smW[(warp-1)*16 + e];
        }
    } else if (warp == 0) {
        #pragma unroll
        for (int e = 0; e < 16; e++) P[e] = Mp[e];
    } else {
        float E[16];
        #pragma unroll
        for (int e = 0; e < 16; e++) E[e] = smW[(warp-1)*16 + e];
        mm4(Mp, E, P);
    }
    #pragma unroll
    for (int e = 0; e < 16; e++) smP[i*17 + e] = P[e];
    __syncthreads();

    // rotate: thread handles timesteps t = j*NCHUNK + i (coalesced g_L reads)
    for (int j = 0; j < CHUNK; j++) {
        int t  = j*NCHUNK + i;
        int ch = t >> 3;                 // CHUNK == 8
        const float* Pp = &smP[ch*17];
        int n = b*Tt + t;

        float4 v = *(const float4*)(g_SV + (size_t)n*NCOLS1 + VOFF + h*Nn);
        float u0 = Pp[ 0]*v.x + Pp[ 1]*v.y + Pp[ 2]*v.z + Pp[ 3]*v.w;
        float u1 = Pp[ 4]*v.x + Pp[ 5]*v.y + Pp[ 6]*v.z + Pp[ 7]*v.w;
        float u2 = Pp[ 8]*v.x + Pp[ 9]*v.y + Pp[10]*v.z + Pp[11]*v.w;
        float u3 = Pp[12]*v.x + Pp[13]*v.y + Pp[14]*v.z + Pp[15]*v.w;

        const float* L = g_L + ((size_t)chain*Tt + t)*16;
        float4 l0 = *(const float4*)(L);
        float4 l1 = *(const float4*)(L + 4);
        float4 l2 = *(const float4*)(L + 8);
        float4 l3 = *(const float4*)(L + 12);
        float r0 = l0.x*u0 + l0.y*u1 + l0.z*u2 + l0.w*u3;
        float r1 = l1.x*u0 + l1.y*u1 + l1.z*u2 + l1.w*u3;
        float r2 = l2.x*u0 + l2.y*u1 + l2.z*u2 + l2.w*u3;
        float r3 = l3.x*u0 + l3.y*u1 + l3.z*u2 + l3.w*u3;

        uint2 hi, lo;
        split_pack(make_float4(r0, r1, r2, r3), hi, lo);
        *(uint2*)&g_RotH[(size_t)n*HN + h*Nn] = hi;
        *(uint2*)&g_RotL[(size_t)n*HN + h*Nn] = lo;
    }
}

// ---------------- launcher ----------------
extern "C" void kernel_launch(void* const* d_in, const int* in_sizes, int n_in,
                              void* d_out, int out_size) {
    const float* x     = (const float*)d_in[0];
    const float* Wskew = (const float*)d_in[1];
    const float* Wv    = (const float*)d_in[2];
    const float* Wo    = (const float*)d_in[3];
    float* out = (float*)d_out;

    float *g_SV_p;
    __nv_bfloat16 *b1h, *b1l, *b2h, *b2l, *rh, *rl;
    cudaGetSymbolAddress((void**)&g_SV_p, g_SV);
    cudaGetSymbolAddress((void**)&b1h, g_Bt1H);
    cudaGetSymbolAddress((void**)&b1l, g_Bt1L);
    cudaGetSymbolAddress((void**)&b2h, g_Bt2H);
    cudaGetSymbolAddress((void**)&b2l, g_Bt2L);
    cudaGetSymbolAddress((void**)&rh,  g_RotH);
    cudaGetSymbolAddress((void**)&rl,  g_RotL);

    const int SM1 = 2 * (2*128 + 2*NCOLS1) * 48;   // 55296 B
    const int SM2 = 2 * (2*128 + 2*128) * 48;      // 49152 B
    cudaFuncSetAttribute(gemm_bf16_kernel<NCOLS1, NCOLS1, D_MODEL, false>,
                         cudaFuncAttributeMaxDynamicSharedMemorySize, SM1);
    cudaFuncSetAttribute(gemm_bf16_kernel<128, D_MODEL, HN, true>,
                         cudaFuncAttributeMaxDynamicSharedMemorySize, SM2);

    prep_kernel<<<(NCOLS1*D_MODEL + D_MODEL*HN + 255)/256, 256>>>(Wskew, Wv, Wo);
    gemm_bf16_kernel<NCOLS1, NCOLS1, D_MODEL, false>
        <<<dim3(1, NROWS/128), 256, SM1>>>(x, nullptr, nullptr, b1h, b1l, g_SV_p);
    expm_scan_kernel<<<(CHAINS*NCHUNK + 255)/256, 256>>>();
    prefix_rotate_kernel<<<CHAINS, NCHUNK>>>();
    gemm_bf16_kernel<128, D_MODEL, HN, true>
        <<<dim3(D_MODEL/128, NROWS/128), 256, SM2>>>(nullptr, rh, rl, b2h, b2l, out);
}